// round 3
// baseline (speedup 1.0000x reference)
#include <cuda_runtime.h>
#include <math.h>

#define BQ 8
#define TQ 256
#define KQ 20
#define HQ 768
#define VQ 30522
#define NGQ (4*HQ)      // 3072
#define M2Q ((TQ-1)*BQ) // 2040
#define NVT 239         // ceil(V/128)

// ---------------- device scratch (static, no allocation) ----------------
__device__ float g_em[TQ*BQ*KQ];
__device__ float g_tr[KQ*KQ];
__device__ float g_alpha[TQ*BQ*KQ];
__device__ float g_relaxed[TQ*BQ*KQ];
__device__ __align__(16) float g_decin[M2Q*HQ];
__device__ __align__(16) float g_xg[(size_t)M2Q*NGQ];
__device__ __align__(16) float g_hall[(size_t)M2Q*HQ];
__device__ __align__(16) float g_hbuf[2][BQ*HQ];
__device__ __align__(16) float g_c[BQ*HQ];
__device__ int   g_tgt[M2Q];
__device__ float g_pm[(size_t)M2Q*NVT];
__device__ float g_ps[(size_t)M2Q*NVT];
__device__ float g_tok[M2Q];
__device__ float g_acc[4]; // ent_sum, ent_cnt, plp_sum, plp_cnt

__device__ __forceinline__ float warp_sum(float v){
    #pragma unroll
    for(int o=16;o;o>>=1) v += __shfl_xor_sync(0xffffffffu,v,o);
    return v;
}
__device__ __forceinline__ float warp_maxf(float v){
    #pragma unroll
    for(int o=16;o;o>>=1) v = fmaxf(v,__shfl_xor_sync(0xffffffffu,v,o));
    return v;
}
__device__ __forceinline__ float sigf(float x){ return 1.f/(1.f+expf(-x)); }

// ---------------- init: zero state + accumulators, build targets ----------------
__global__ void k_init(const int* __restrict__ x){
    int i0 = blockIdx.x*blockDim.x + threadIdx.x;
    int stride = gridDim.x*blockDim.x;
    for(int i=i0;i<BQ*HQ;i+=stride){ g_hbuf[0][i]=0.f; g_c[i]=0.f; }
    for(int i=i0;i<M2Q;i+=stride){
        int t=i/BQ, b=i%BQ;
        g_tgt[i] = x[b*TQ + t + 1];
    }
    if(i0<4) g_acc[i0]=0.f;
}

// ---------------- emission [T,B,K] + masked entropy ----------------
__global__ void k_emission(const float* __restrict__ xe, const float* __restrict__ S,
                           const int* __restrict__ attn){
    int w = threadIdx.x>>5, lane = threadIdx.x&31;
    int p = blockIdx.x*8 + w;            // 0..2047
    int t = p / BQ, b = p % BQ;
    const float* xrow = xe + ((size_t)b*TQ + t)*HQ;
    float acc[KQ];
    #pragma unroll
    for(int k=0;k<KQ;k++) acc[k]=0.f;
    for(int h=lane;h<HQ;h+=32){
        float xv = xrow[h];
        #pragma unroll
        for(int k=0;k<KQ;k++) acc[k] += xv * S[k*HQ+h];
    }
    #pragma unroll
    for(int k=0;k<KQ;k++) acc[k] = warp_sum(acc[k]);
    if(lane<KQ) g_em[(t*BQ+b)*KQ+lane] = acc[lane];
    if(lane==0){
        float m=-INFINITY;
        #pragma unroll
        for(int k=0;k<KQ;k++) m=fmaxf(m,acc[k]);
        float s=0.f;
        #pragma unroll
        for(int k=0;k<KQ;k++) s+=expf(acc[k]-m);
        float lse=m+logf(s);
        float ent=0.f;
        #pragma unroll
        for(int k=0;k<KQ;k++){ float lp=acc[k]-lse; ent -= expf(lp)*lp; }
        float mk=(float)attn[b*TQ+t];
        atomicAdd(&g_acc[0], ent*mk);
        atomicAdd(&g_acc[1], mk);
    }
}

// ---------------- transition = S @ S^T ----------------
__global__ void k_transition(const float* __restrict__ S){
    int wi = blockIdx.x*8 + (threadIdx.x>>5);
    int lane = threadIdx.x&31;
    if(wi>=KQ*KQ) return;
    int i=wi/KQ, j=wi%KQ;
    float a=0.f;
    for(int h=lane;h<HQ;h+=32) a += S[i*HQ+h]*S[j*HQ+h];
    a = warp_sum(a);
    if(lane==0) g_tr[wi]=a;
}

// ---------------- CRF forward scan + relaxed backward sampling ----------------
// one block, warp w = batch b, lane = state k (lanes >= 20 inert)
__global__ void k_crf(const float* __restrict__ gumbel, float* __restrict__ out, int out_size){
    __shared__ float tr_s[KQ*KQ];
    int tid=threadIdx.x;
    for(int i=tid;i<KQ*KQ;i+=256) tr_s[i]=g_tr[i];
    __syncthreads();
    int b = tid>>5, lane = tid&31;
    const unsigned FULL=0xffffffffu;
    bool act = lane<KQ;
    int kl = act ? lane : 0;

    float a = act ? g_em[(0*BQ+b)*KQ+lane] : -INFINITY;
    if(act) g_alpha[(0*BQ+b)*KQ+lane] = a;
    for(int t=1;t<TQ;t++){
        float vbuf[KQ];
        float m=-INFINITY;
        #pragma unroll
        for(int kp=0;kp<KQ;kp++){
            float av = __shfl_sync(FULL, a, kp);
            float v = av + tr_s[kp*KQ+kl];
            vbuf[kp]=v; m=fmaxf(m,v);
        }
        float s=0.f;
        #pragma unroll
        for(int kp=0;kp<KQ;kp++) s += expf(vbuf[kp]-m);
        float em = act ? g_em[(t*BQ+b)*KQ+lane] : -INFINITY;
        a = m + logf(s) + em;
        if(act) g_alpha[(t*BQ+b)*KQ+lane]=a;
    }
    // backward, t = T-1 first (uses alpha register directly)
    int zn = 0;
    {
        float v = act ? a : -INFINITY;
        float m = warp_maxf(v);
        float s = warp_sum(act ? expf(v-m) : 0.f);
        float lse = m + logf(s);
        float lg = v - lse;
        float y = act ? (lg + gumbel[((TQ-1)*BQ+b)*KQ+lane]) : -INFINITY;
        float ym=y; int yi=act?lane:KQ;
        #pragma unroll
        for(int o=16;o;o>>=1){
            float om=__shfl_xor_sync(FULL,ym,o);
            int   oi=__shfl_xor_sync(FULL,yi,o);
            if(om>ym || (om==ym && oi<yi)){ ym=om; yi=oi; }
        }
        zn = yi;
        float es = act ? expf(y-ym) : 0.f;
        float ss = warp_sum(es);
        if(act) g_relaxed[((TQ-1)*BQ+b)*KQ+lane] = es/ss;
        if(lane==0){
            int oi = 1 + b*TQ + (TQ-1);
            if(oi < out_size) out[oi] = (float)zn;
        }
    }
    for(int t=TQ-2;t>=0;t--){
        float v = act ? (g_alpha[(t*BQ+b)*KQ+lane] + tr_s[lane*KQ+zn]) : -INFINITY;
        float m = warp_maxf(v);
        float s = warp_sum(act ? expf(v-m) : 0.f);
        float lse = m + logf(s);
        float lg = v - lse;
        float y = act ? (lg + gumbel[((size_t)t*BQ+b)*KQ+lane]) : -INFINITY;
        float ym=y; int yi=act?lane:KQ;
        #pragma unroll
        for(int o=16;o;o>>=1){
            float om=__shfl_xor_sync(FULL,ym,o);
            int   oi=__shfl_xor_sync(FULL,yi,o);
            if(om>ym || (om==ym && oi<yi)){ ym=om; yi=oi; }
        }
        zn = yi;
        float es = act ? expf(y-ym) : 0.f;
        float ss = warp_sum(es);
        if(act) g_relaxed[((size_t)t*BQ+b)*KQ+lane] = es/ss;
        if(lane==0){
            int oi = 1 + b*TQ + t;
            if(oi < out_size) out[oi] = (float)zn;
        }
    }
}

// ---------------- dec_in[t,b,:] = relaxed @ S + word_emb ----------------
__global__ void k_decin(const float* __restrict__ S, const float* __restrict__ emb,
                        const int* __restrict__ x){
    int r = blockIdx.x;                  // 0..M2-1, r = t*B+b
    int t = r/BQ, b = r%BQ;
    float rel[KQ];
    const float* rp = &g_relaxed[(t*BQ+b)*KQ];
    #pragma unroll
    for(int k=0;k<KQ;k++) rel[k]=rp[k];
    int xi = x[b*TQ+t];
    const float* erow = emb + (size_t)xi*HQ;
    for(int h=threadIdx.x;h<HQ;h+=blockDim.x){
        float v = erow[h];
        #pragma unroll
        for(int k=0;k<KQ;k++) v += rel[k]*S[k*HQ+h];
        g_decin[(size_t)r*HQ+h]=v;
    }
}

// ---------------- GEMM (NT) X_gates = dec_in @ W_ih^T + b_lstm ----------------
__global__ void k_gemm_xg(const float* __restrict__ Wih, const float* __restrict__ bl){
    __shared__ __align__(16) float As[16][128];
    __shared__ __align__(16) float Bs[16][128];
    const float* A = g_decin;
    int tid=threadIdx.x;
    int tx=tid&15, ty=tid>>4;
    int row0=blockIdx.y*128, col0=blockIdx.x*128;
    float acc[8][8];
    #pragma unroll
    for(int i=0;i<8;i++)
        #pragma unroll
        for(int j=0;j<8;j++) acc[i][j]=0.f;
    for(int k0=0;k0<HQ;k0+=16){
        #pragma unroll
        for(int i=0;i<2;i++){
            int id=tid*2+i;
            int r=id>>2, kq=(id&3)<<2;
            int gr=row0+r, gc=col0+r;
            float4 va = make_float4(0,0,0,0), vb = va;
            if(gr<M2Q) va = *(const float4*)(A + (size_t)gr*HQ + k0+kq);
            vb = *(const float4*)(Wih + (size_t)gc*HQ + k0+kq);
            As[kq][r]=va.x; As[kq+1][r]=va.y; As[kq+2][r]=va.z; As[kq+3][r]=va.w;
            Bs[kq][r]=vb.x; Bs[kq+1][r]=vb.y; Bs[kq+2][r]=vb.z; Bs[kq+3][r]=vb.w;
        }
        __syncthreads();
        #pragma unroll
        for(int kk=0;kk<16;kk++){
            float ra[8],rb[8];
            #pragma unroll
            for(int i=0;i<8;i++){ ra[i]=As[kk][ty*8+i]; rb[i]=Bs[kk][tx*8+i]; }
            #pragma unroll
            for(int i=0;i<8;i++)
                #pragma unroll
                for(int j=0;j<8;j++) acc[i][j] += ra[i]*rb[j];
        }
        __syncthreads();
    }
    #pragma unroll
    for(int i=0;i<8;i++){
        int r=row0+ty*8+i; if(r>=M2Q) continue;
        #pragma unroll
        for(int j=0;j<8;j++){
            int c=col0+tx*8+j;
            g_xg[(size_t)r*NGQ+c]=acc[i][j]+bl[c];
        }
    }
}

// ---------------- one LSTM step ----------------
// block handles 8 hidden units (32 W_hh rows), grid = 96
__global__ void k_lstm(const float* __restrict__ Whh, int t){
    __shared__ __align__(16) float hs[BQ*HQ];          // 24KB
    __shared__ float gs[32][8];
    int tid=threadIdx.x;
    const float* hin = g_hbuf[t&1];
    float* hout = g_hbuf[(t+1)&1];
    for(int i=tid;i<BQ*HQ/4;i+=256) ((float4*)hs)[i]=((const float4*)hin)[i];
    __syncthreads();
    int u0 = blockIdx.x*8;
    int w=tid>>5, lane=tid&31;
    float acc[4][8];
    #pragma unroll
    for(int j=0;j<4;j++)
        #pragma unroll
        for(int b2=0;b2<8;b2++) acc[j][b2]=0.f;
    int rows[4];
    #pragma unroll
    for(int j=0;j<4;j++){ int q=w*4+j; int g=q>>3, uu=q&7; rows[j]=g*HQ + u0+uu; }
    for(int h=lane;h<HQ;h+=32){
        float hv[8];
        #pragma unroll
        for(int b2=0;b2<8;b2++) hv[b2]=hs[b2*HQ+h];
        #pragma unroll
        for(int j=0;j<4;j++){
            float wv = Whh[(size_t)rows[j]*HQ + h];
            #pragma unroll
            for(int b2=0;b2<8;b2++) acc[j][b2] += wv*hv[b2];
        }
    }
    #pragma unroll
    for(int j=0;j<4;j++)
        #pragma unroll
        for(int b2=0;b2<8;b2++){
            float v=acc[j][b2];
            #pragma unroll
            for(int o=16;o;o>>=1) v += __shfl_xor_sync(0xffffffffu,v,o);
            if(lane==0) gs[w*4+j][b2]=v;
        }
    __syncthreads();
    if(tid<64){
        int uu=tid>>3, b2=tid&7;
        int r=t*BQ+b2;
        const float* xr = &g_xg[(size_t)r*NGQ];
        float gi = gs[0*8+uu][b2] + xr[0*HQ + u0+uu];
        float gf = gs[1*8+uu][b2] + xr[1*HQ + u0+uu];
        float gg = gs[2*8+uu][b2] + xr[2*HQ + u0+uu];
        float go = gs[3*8+uu][b2] + xr[3*HQ + u0+uu];
        int hidx = b2*HQ + u0+uu;
        float c = sigf(gf)*g_c[hidx] + sigf(gi)*tanhf(gg);
        float hv = sigf(go)*tanhf(c);
        g_c[hidx]=c; hout[hidx]=hv;
        g_hall[(size_t)r*HQ + u0+uu]=hv;
    }
}

// ---------------- fused GEMM (NT) + per-tile logsumexp partials + target capture ----------------
__global__ void k_gemm_lse(const float* __restrict__ Wout, const float* __restrict__ bo){
    __shared__ __align__(16) float As[16][128];
    __shared__ __align__(16) float Bs[16][128];
    __shared__ float red[128][17];
    const float* A = g_hall;
    int tid=threadIdx.x;
    int tx=tid&15, ty=tid>>4;
    int row0=blockIdx.y*128, col0=blockIdx.x*128;
    float acc[8][8];
    #pragma unroll
    for(int i=0;i<8;i++)
        #pragma unroll
        for(int j=0;j<8;j++) acc[i][j]=0.f;
    for(int k0=0;k0<HQ;k0+=16){
        #pragma unroll
        for(int i=0;i<2;i++){
            int id=tid*2+i;
            int r=id>>2, kq=(id&3)<<2;
            int gr=row0+r, gc=col0+r;
            float4 va = make_float4(0,0,0,0), vb = va;
            if(gr<M2Q) va = *(const float4*)(A + (size_t)gr*HQ + k0+kq);
            if(gc<VQ)  vb = *(const float4*)(Wout + (size_t)gc*HQ + k0+kq);
            As[kq][r]=va.x; As[kq+1][r]=va.y; As[kq+2][r]=va.z; As[kq+3][r]=va.w;
            Bs[kq][r]=vb.x; Bs[kq+1][r]=vb.y; Bs[kq+2][r]=vb.z; Bs[kq+3][r]=vb.w;
        }
        __syncthreads();
        #pragma unroll
        for(int kk=0;kk<16;kk++){
            float ra[8],rb[8];
            #pragma unroll
            for(int i=0;i<8;i++){ ra[i]=As[kk][ty*8+i]; rb[i]=Bs[kk][tx*8+i]; }
            #pragma unroll
            for(int i=0;i<8;i++)
                #pragma unroll
                for(int j=0;j<8;j++) acc[i][j] += ra[i]*rb[j];
        }
        __syncthreads();
    }
    // epilogue: bias + per-row tile max / sumexp
    bool cval[8]; float bz[8];
    #pragma unroll
    for(int j=0;j<8;j++){
        int c=col0+tx*8+j;
        cval[j] = (c<VQ);
        bz[j] = cval[j] ? bo[c] : 0.f;
    }
    #pragma unroll
    for(int i=0;i<8;i++){
        float m=-INFINITY;
        #pragma unroll
        for(int j=0;j<8;j++){
            if(cval[j]){ acc[i][j]+=bz[j]; m=fmaxf(m,acc[i][j]); }
            else acc[i][j]=-INFINITY;
        }
        red[ty*8+i][tx]=m;
    }
    __syncthreads();
    if(tid<128){
        float m=-INFINITY;
        #pragma unroll
        for(int q=0;q<16;q++) m=fmaxf(m,red[tid][q]);
        red[tid][16]=m;
    }
    __syncthreads();
    #pragma unroll
    for(int i=0;i<8;i++){
        float rm = red[ty*8+i][16];
        float s=0.f;
        #pragma unroll
        for(int j=0;j<8;j++) if(cval[j]) s += expf(acc[i][j]-rm);
        red[ty*8+i][tx]=s;
    }
    __syncthreads();
    if(tid<128){
        int r=row0+tid;
        if(r<M2Q){
            float s=0.f;
            #pragma unroll
            for(int q=0;q<16;q++) s+=red[tid][q];
            g_pm[(size_t)r*NVT + blockIdx.x]=red[tid][16];
            g_ps[(size_t)r*NVT + blockIdx.x]=s;
        }
    }
    #pragma unroll
    for(int i=0;i<8;i++){
        int r=row0+ty*8+i;
        if(r<M2Q){
            int lo = g_tgt[r]-col0;
            if(lo>=0 && lo<128 && (lo>>3)==tx) g_tok[r]=acc[i][lo&7];
        }
    }
}

// ---------------- combine LSE partials, accumulate p_log_prob ----------------
__global__ void k_lse_reduce(const int* __restrict__ attn){
    int r = blockIdx.x*blockDim.x + threadIdx.x;
    if(r>=M2Q) return;
    const float* pm = &g_pm[(size_t)r*NVT];
    const float* ps = &g_ps[(size_t)r*NVT];
    float m=-INFINITY;
    for(int q=0;q<NVT;q++) m=fmaxf(m,pm[q]);
    float s=0.f;
    for(int q=0;q<NVT;q++) s += ps[q]*expf(pm[q]-m);
    float lse = m + logf(s);
    float tlp = g_tok[r]-lse;
    int t=r/BQ, b=r%BQ;
    float mk=(float)attn[b*TQ + t + 1];
    atomicAdd(&g_acc[2], tlp*mk);
    atomicAdd(&g_acc[3], mk);
}

__global__ void k_finalize(float* __restrict__ out){
    out[0] = -(g_acc[2]/g_acc[3] + g_acc[0]/g_acc[1]);
}

// ---------------- launch ----------------
extern "C" void kernel_launch(void* const* d_in, const int* in_sizes, int n_in,
                              void* d_out, int out_size){
    const float* x_emb  = (const float*)d_in[0];
    const float* S      = (const float*)d_in[1];
    const float* emb    = (const float*)d_in[2];
    const float* W_ih   = (const float*)d_in[3];
    const float* W_hh   = (const float*)d_in[4];
    const float* b_lstm = (const float*)d_in[5];
    const float* W_out  = (const float*)d_in[6];
    const float* b_out  = (const float*)d_in[7];
    const float* gumbel = (const float*)d_in[8];
    const int*   x      = (const int*)d_in[9];
    const int*   attn   = (const int*)d_in[10];
    float* out = (float*)d_out;

    k_init<<<32,256>>>(x);
    k_emission<<<256,256>>>(x_emb,S,attn);
    k_transition<<<50,256>>>(S);
    k_crf<<<1,256>>>(gumbel,out,out_size);
    k_decin<<<M2Q,128>>>(S,emb,x);
    k_gemm_xg<<<dim3(NGQ/128,16),256>>>(W_ih,b_lstm);
    for(int t=0;t<TQ-1;t++)
        k_lstm<<<96,256>>>(W_hh,t);
    k_gemm_lse<<<dim3(NVT,16),256>>>(W_out,b_out);
    k_lse_reduce<<<8,256>>>(attn);
    k_finalize<<<1,1>>>(out);
}

// round 4
// speedup vs baseline: 2.1584x; 2.1584x over previous
#include <cuda_runtime.h>
#include <cuda_bf16.h>
#include <math.h>

#define BQ 8
#define TQ 256
#define KQ 20
#define HQ 768
#define VQ 30522
#define NGQ (4*HQ)      // 3072
#define M2Q ((TQ-1)*BQ) // 2040
#define NVT 239         // ceil(V/128)
#define MPAD 2048
#define NPAD (NVT*128)  // 30592
#define LBLK 96

// ---------------- device scratch (static, no allocation) ----------------
__device__ float g_em[TQ*BQ*KQ];
__device__ float g_tr[KQ*KQ];
__device__ float g_alpha[TQ*BQ*KQ];
__device__ float g_relaxed[TQ*BQ*KQ];
__device__ __align__(16) float g_decin[M2Q*HQ];
__device__ __align__(16) float g_xg[(size_t)M2Q*NGQ];
__device__ __align__(16) float g_hall[(size_t)M2Q*HQ];
__device__ __align__(16) float g_hbuf[2][BQ*HQ];
__device__ __align__(16) __nv_bfloat16 g_hallb[(size_t)MPAD*HQ];
__device__ __align__(16) __nv_bfloat16 g_woutb[(size_t)NPAD*HQ];
__device__ int   g_tgt[M2Q];
__device__ float g_pm[(size_t)M2Q*NVT];
__device__ float g_ps[(size_t)M2Q*NVT];
__device__ float g_tok[M2Q];
__device__ float g_acc[4]; // ent_sum, ent_cnt, plp_sum, plp_cnt
__device__ unsigned g_bar;

__device__ __forceinline__ float warp_sum(float v){
    #pragma unroll
    for(int o=16;o;o>>=1) v += __shfl_xor_sync(0xffffffffu,v,o);
    return v;
}
__device__ __forceinline__ float warp_maxf(float v){
    #pragma unroll
    for(int o=16;o;o>>=1) v = fmaxf(v,__shfl_xor_sync(0xffffffffu,v,o));
    return v;
}
__device__ __forceinline__ float sigf(float x){ return 1.f/(1.f+__expf(-x)); }

// ---------------- init ----------------
__global__ void k_init(const int* __restrict__ x){
    int i0 = blockIdx.x*blockDim.x + threadIdx.x;
    int stride = gridDim.x*blockDim.x;
    for(int i=i0;i<BQ*HQ;i+=stride){ g_hbuf[0][i]=0.f; }
    for(int i=i0;i<M2Q;i+=stride){
        int t=i/BQ, b=i%BQ;
        g_tgt[i] = x[b*TQ + t + 1];
    }
    if(i0<4) g_acc[i0]=0.f;
    if(i0==0) g_bar=0u;
}

// ---------------- W_out fp32 -> bf16 (padded rows zero) ----------------
__global__ void k_cvt_wout(const float* __restrict__ W){
    size_t i4 = (size_t)blockIdx.x*blockDim.x + threadIdx.x;
    size_t base = i4*4;
    if(base >= (size_t)NPAD*HQ) return;
    size_t r = base / HQ;
    __nv_bfloat162 o0, o1;
    if(r < VQ){
        float4 v = *(const float4*)(W + base);
        o0 = __floats2bfloat162_rn(v.x, v.y);
        o1 = __floats2bfloat162_rn(v.z, v.w);
    } else {
        o0 = __floats2bfloat162_rn(0.f,0.f); o1 = o0;
    }
    *(__nv_bfloat162*)(g_woutb + base)     = o0;
    *(__nv_bfloat162*)(g_woutb + base + 2) = o1;
}

// ---------------- hall fp32 -> bf16 (padded rows zero) ----------------
__global__ void k_cvt_hall(){
    size_t i4 = (size_t)blockIdx.x*blockDim.x + threadIdx.x;
    size_t base = i4*4;
    if(base >= (size_t)MPAD*HQ) return;
    size_t r = base / HQ;
    __nv_bfloat162 o0, o1;
    if(r < M2Q){
        float4 v = *(const float4*)(g_hall + base);
        o0 = __floats2bfloat162_rn(v.x, v.y);
        o1 = __floats2bfloat162_rn(v.z, v.w);
    } else {
        o0 = __floats2bfloat162_rn(0.f,0.f); o1 = o0;
    }
    *(__nv_bfloat162*)(g_hallb + base)     = o0;
    *(__nv_bfloat162*)(g_hallb + base + 2) = o1;
}

// ---------------- emission [T,B,K] + masked entropy ----------------
__global__ void k_emission(const float* __restrict__ xe, const float* __restrict__ S,
                           const int* __restrict__ attn){
    int w = threadIdx.x>>5, lane = threadIdx.x&31;
    int p = blockIdx.x*8 + w;
    int t = p / BQ, b = p % BQ;
    const float* xrow = xe + ((size_t)b*TQ + t)*HQ;
    float acc[KQ];
    #pragma unroll
    for(int k=0;k<KQ;k++) acc[k]=0.f;
    for(int h=lane;h<HQ;h+=32){
        float xv = xrow[h];
        #pragma unroll
        for(int k=0;k<KQ;k++) acc[k] += xv * S[k*HQ+h];
    }
    #pragma unroll
    for(int k=0;k<KQ;k++) acc[k] = warp_sum(acc[k]);
    if(lane<KQ) g_em[(t*BQ+b)*KQ+lane] = acc[lane];
    if(lane==0){
        float m=-INFINITY;
        #pragma unroll
        for(int k=0;k<KQ;k++) m=fmaxf(m,acc[k]);
        float s=0.f;
        #pragma unroll
        for(int k=0;k<KQ;k++) s+=__expf(acc[k]-m);
        float lse=m+__logf(s);
        float ent=0.f;
        #pragma unroll
        for(int k=0;k<KQ;k++){ float lp=acc[k]-lse; ent -= __expf(lp)*lp; }
        float mk=(float)attn[b*TQ+t];
        atomicAdd(&g_acc[0], ent*mk);
        atomicAdd(&g_acc[1], mk);
    }
}

// ---------------- transition = S @ S^T ----------------
__global__ void k_transition(const float* __restrict__ S){
    int wi = blockIdx.x*8 + (threadIdx.x>>5);
    int lane = threadIdx.x&31;
    if(wi>=KQ*KQ) return;
    int i=wi/KQ, j=wi%KQ;
    float a=0.f;
    for(int h=lane;h<HQ;h+=32) a += S[i*HQ+h]*S[j*HQ+h];
    a = warp_sum(a);
    if(lane==0) g_tr[wi]=a;
}

// ---------------- CRF forward scan + relaxed backward sampling ----------------
__global__ void k_crf(const float* __restrict__ gumbel, float* __restrict__ out, int out_size){
    __shared__ float tr_s[KQ*KQ];
    int tid=threadIdx.x;
    for(int i=tid;i<KQ*KQ;i+=256) tr_s[i]=g_tr[i];
    __syncthreads();
    int b = tid>>5, lane = tid&31;
    const unsigned FULL=0xffffffffu;
    bool act = lane<KQ;
    int kl = act ? lane : 0;

    float a = act ? g_em[(0*BQ+b)*KQ+lane] : -INFINITY;
    if(act) g_alpha[(0*BQ+b)*KQ+lane] = a;
    for(int t=1;t<TQ;t++){
        float vbuf[KQ];
        float m=-INFINITY;
        #pragma unroll
        for(int kp=0;kp<KQ;kp++){
            float av = __shfl_sync(FULL, a, kp);
            float v = av + tr_s[kp*KQ+kl];
            vbuf[kp]=v; m=fmaxf(m,v);
        }
        float s=0.f;
        #pragma unroll
        for(int kp=0;kp<KQ;kp++) s += __expf(vbuf[kp]-m);
        float em = act ? g_em[(t*BQ+b)*KQ+lane] : -INFINITY;
        a = m + __logf(s) + em;
        if(act) g_alpha[(t*BQ+b)*KQ+lane]=a;
    }
    int zn = 0;
    {
        float v = act ? a : -INFINITY;
        float m = warp_maxf(v);
        float s = warp_sum(act ? __expf(v-m) : 0.f);
        float lse = m + __logf(s);
        float lg = v - lse;
        float y = act ? (lg + gumbel[((TQ-1)*BQ+b)*KQ+lane]) : -INFINITY;
        float ym=y; int yi=act?lane:KQ;
        #pragma unroll
        for(int o=16;o;o>>=1){
            float om=__shfl_xor_sync(FULL,ym,o);
            int   oi=__shfl_xor_sync(FULL,yi,o);
            if(om>ym || (om==ym && oi<yi)){ ym=om; yi=oi; }
        }
        zn = yi;
        float es = act ? __expf(y-ym) : 0.f;
        float ss = warp_sum(es);
        if(act) g_relaxed[((TQ-1)*BQ+b)*KQ+lane] = es/ss;
        if(lane==0){
            int oi = 1 + b*TQ + (TQ-1);
            if(oi < out_size) out[oi] = (float)zn;
        }
    }
    for(int t=TQ-2;t>=0;t--){
        float v = act ? (g_alpha[(t*BQ+b)*KQ+lane] + tr_s[lane*KQ+zn]) : -INFINITY;
        float m = warp_maxf(v);
        float s = warp_sum(act ? __expf(v-m) : 0.f);
        float lse = m + __logf(s);
        float lg = v - lse;
        float y = act ? (lg + gumbel[((size_t)t*BQ+b)*KQ+lane]) : -INFINITY;
        float ym=y; int yi=act?lane:KQ;
        #pragma unroll
        for(int o=16;o;o>>=1){
            float om=__shfl_xor_sync(FULL,ym,o);
            int   oi=__shfl_xor_sync(FULL,yi,o);
            if(om>ym || (om==ym && oi<yi)){ ym=om; yi=oi; }
        }
        zn = yi;
        float es = act ? __expf(y-ym) : 0.f;
        float ss = warp_sum(es);
        if(act) g_relaxed[((size_t)t*BQ+b)*KQ+lane] = es/ss;
        if(lane==0){
            int oi = 1 + b*TQ + t;
            if(oi < out_size) out[oi] = (float)zn;
        }
    }
}

// ---------------- dec_in ----------------
__global__ void k_decin(const float* __restrict__ S, const float* __restrict__ emb,
                        const int* __restrict__ x){
    int r = blockIdx.x;
    int t = r/BQ, b = r%BQ;
    float rel[KQ];
    const float* rp = &g_relaxed[(t*BQ+b)*KQ];
    #pragma unroll
    for(int k=0;k<KQ;k++) rel[k]=rp[k];
    int xi = x[b*TQ+t];
    const float* erow = emb + (size_t)xi*HQ;
    for(int h=threadIdx.x;h<HQ;h+=blockDim.x){
        float v = erow[h];
        #pragma unroll
        for(int k=0;k<KQ;k++) v += rel[k]*S[k*HQ+h];
        g_decin[(size_t)r*HQ+h]=v;
    }
}

// ---------------- GEMM (NT) X_gates = dec_in @ W_ih^T + b_lstm (fp32) ----------------
__global__ void k_gemm_xg(const float* __restrict__ Wih, const float* __restrict__ bl){
    __shared__ __align__(16) float As[16][128];
    __shared__ __align__(16) float Bs[16][128];
    const float* A = g_decin;
    int tid=threadIdx.x;
    int tx=tid&15, ty=tid>>4;
    int row0=blockIdx.y*128, col0=blockIdx.x*128;
    float acc[8][8];
    #pragma unroll
    for(int i=0;i<8;i++)
        #pragma unroll
        for(int j=0;j<8;j++) acc[i][j]=0.f;
    for(int k0=0;k0<HQ;k0+=16){
        #pragma unroll
        for(int i=0;i<2;i++){
            int id=tid*2+i;
            int r=id>>2, kq=(id&3)<<2;
            int gr=row0+r, gc=col0+r;
            float4 va = make_float4(0,0,0,0), vb = va;
            if(gr<M2Q) va = *(const float4*)(A + (size_t)gr*HQ + k0+kq);
            vb = *(const float4*)(Wih + (size_t)gc*HQ + k0+kq);
            As[kq][r]=va.x; As[kq+1][r]=va.y; As[kq+2][r]=va.z; As[kq+3][r]=va.w;
            Bs[kq][r]=vb.x; Bs[kq+1][r]=vb.y; Bs[kq+2][r]=vb.z; Bs[kq+3][r]=vb.w;
        }
        __syncthreads();
        #pragma unroll
        for(int kk=0;kk<16;kk++){
            float ra[8],rb[8];
            #pragma unroll
            for(int i=0;i<8;i++){ ra[i]=As[kk][ty*8+i]; rb[i]=Bs[kk][tx*8+i]; }
            #pragma unroll
            for(int i=0;i<8;i++)
                #pragma unroll
                for(int j=0;j<8;j++) acc[i][j] += ra[i]*rb[j];
        }
        __syncthreads();
    }
    #pragma unroll
    for(int i=0;i<8;i++){
        int r=row0+ty*8+i; if(r>=M2Q) continue;
        #pragma unroll
        for(int j=0;j<8;j++){
            int c=col0+tx*8+j;
            g_xg[(size_t)r*NGQ+c]=acc[i][j]+bl[c];
        }
    }
}

// ---------------- persistent LSTM: all 255 steps in one kernel ----------------
// grid=96 blocks (all co-resident), block handles 8 hidden units.
// W_hh slice cached in SMEM; cell state in registers; global spin barrier.
__global__ void __launch_bounds__(256,1) k_lstm_persist(const float* __restrict__ Whh){
    extern __shared__ float sm[];
    float* Wsh = sm;                  // 32*768 floats
    float* hs  = sm + 32*HQ;          // 6144 floats
    float* gs  = sm + 32*HQ + BQ*HQ;  // 32*8 floats
    int tid = threadIdx.x;
    int u0 = blockIdx.x * 8;
    // cache W_hh slice: smem row q (gate g=q>>3, unit uu=q&7) = global row g*HQ+u0+uu
    for(int i=tid; i<32*HQ; i+=256){
        int q = i / HQ, h = i - q*HQ;
        Wsh[i] = Whh[(size_t)((q>>3)*HQ + u0 + (q&7))*HQ + h];
    }
    int w = tid>>5, lane = tid&31;
    float creg = 0.f;
    for(int t=0;t<TQ-1;t++){
        if(tid==0 && t>0){
            while(*(volatile unsigned*)&g_bar < (unsigned)(LBLK*t)) {}
            __threadfence();
        }
        __syncthreads();
        const float* hin = g_hbuf[t&1];
        for(int i=tid;i<BQ*HQ/4;i+=256) ((float4*)hs)[i]=((const float4*)hin)[i];
        __syncthreads();
        float acc[4][8];
        #pragma unroll
        for(int j=0;j<4;j++)
            #pragma unroll
            for(int b2=0;b2<8;b2++) acc[j][b2]=0.f;
        for(int h=lane;h<HQ;h+=32){
            float hv[8];
            #pragma unroll
            for(int b2=0;b2<8;b2++) hv[b2]=hs[b2*HQ+h];
            #pragma unroll
            for(int j=0;j<4;j++){
                float wv = Wsh[(w*4+j)*HQ + h];
                #pragma unroll
                for(int b2=0;b2<8;b2++) acc[j][b2] += wv*hv[b2];
            }
        }
        #pragma unroll
        for(int j=0;j<4;j++)
            #pragma unroll
            for(int b2=0;b2<8;b2++){
                float v=acc[j][b2];
                #pragma unroll
                for(int o=16;o;o>>=1) v += __shfl_xor_sync(0xffffffffu,v,o);
                if(lane==0) gs[(w*4+j)*8 + b2]=v;
            }
        __syncthreads();
        if(tid<64){
            int uu=tid>>3, b2=tid&7;
            int r=t*BQ+b2;
            const float* xr = &g_xg[(size_t)r*NGQ];
            float gi = gs[(0*8+uu)*8+b2] + xr[0*HQ + u0+uu];
            float gf = gs[(1*8+uu)*8+b2] + xr[1*HQ + u0+uu];
            float gg = gs[(2*8+uu)*8+b2] + xr[2*HQ + u0+uu];
            float go = gs[(3*8+uu)*8+b2] + xr[3*HQ + u0+uu];
            creg = sigf(gf)*creg + sigf(gi)*tanhf(gg);
            float hv = sigf(go)*tanhf(creg);
            int hidx = b2*HQ + u0+uu;
            g_hbuf[(t+1)&1][hidx]=hv;
            g_hall[(size_t)r*HQ + u0+uu]=hv;
            __threadfence();
        }
        __syncthreads();
        if(tid==0) atomicAdd(&g_bar, 1u);
    }
}

// ---------------- bf16 tensor-core GEMM + fused LSE epilogue ----------------
// C[2048,30592] = hallb @ woutb^T; block 128x128, warp 64x32, mma m16n8k16
__global__ void __launch_bounds__(256) k_gemm_lse_bf16(const float* __restrict__ bo){
    __shared__ __align__(16) __nv_bfloat16 As[128][40];
    __shared__ __align__(16) __nv_bfloat16 Bs[128][40];
    __shared__ float red[128][4];
    __shared__ float rowmax[128];
    int tid=threadIdx.x;
    int lane=tid&31, wid=tid>>5;
    int wm=wid>>2, wn=wid&3;
    int row0=blockIdx.y*128, col0=blockIdx.x*128;
    float acc[4][4][4];
    #pragma unroll
    for(int a=0;a<4;a++)
        #pragma unroll
        for(int b=0;b<4;b++)
            #pragma unroll
            for(int c=0;c<4;c++) acc[a][b][c]=0.f;
    unsigned asA=(unsigned)__cvta_generic_to_shared(&As[0][0]);
    unsigned asB=(unsigned)__cvta_generic_to_shared(&Bs[0][0]);

    for(int k0=0;k0<HQ;k0+=32){
        #pragma unroll
        for(int i=0;i<2;i++){
            int cid = tid + 256*i;
            int r = cid>>2, ch = cid&3;
            uint4 va = *(const uint4*)(g_hallb + (size_t)(row0+r)*HQ + k0 + ch*8);
            *(uint4*)(&As[r][ch*8]) = va;
            uint4 vb = *(const uint4*)(g_woutb + (size_t)(col0+r)*HQ + k0 + ch*8);
            *(uint4*)(&Bs[r][ch*8]) = vb;
        }
        __syncthreads();
        // B fragments: nt tile, 4 regs = (b0,b1) of ks0 and ks1
        unsigned b[4][4];
        #pragma unroll
        for(int nt=0;nt<4;nt++){
            unsigned addr = asB + ((wn*32 + nt*8 + (lane&7))*40 + (lane>>3)*8)*2;
            asm volatile("ldmatrix.sync.aligned.m8n8.x4.shared.b16 {%0,%1,%2,%3}, [%4];"
                : "=r"(b[nt][0]),"=r"(b[nt][1]),"=r"(b[nt][2]),"=r"(b[nt][3]) : "r"(addr));
        }
        #pragma unroll
        for(int ks=0;ks<2;ks++){
            unsigned a[4][4];
            #pragma unroll
            for(int mt=0;mt<4;mt++){
                unsigned addr = asA + ((wm*64 + mt*16 + (lane&15))*40 + ks*16 + (lane>>4)*8)*2;
                asm volatile("ldmatrix.sync.aligned.m8n8.x4.shared.b16 {%0,%1,%2,%3}, [%4];"
                    : "=r"(a[mt][0]),"=r"(a[mt][1]),"=r"(a[mt][2]),"=r"(a[mt][3]) : "r"(addr));
            }
            #pragma unroll
            for(int mt=0;mt<4;mt++)
                #pragma unroll
                for(int nt=0;nt<4;nt++){
                    asm volatile("mma.sync.aligned.m16n8k16.row.col.f32.bf16.bf16.f32 "
                        "{%0,%1,%2,%3}, {%4,%5,%6,%7}, {%8,%9}, {%0,%1,%2,%3};"
                        : "+f"(acc[mt][nt][0]),"+f"(acc[mt][nt][1]),
                          "+f"(acc[mt][nt][2]),"+f"(acc[mt][nt][3])
                        : "r"(a[mt][0]),"r"(a[mt][1]),"r"(a[mt][2]),"r"(a[mt][3]),
                          "r"(b[nt][ks*2]),"r"(b[nt][ks*2+1]));
                }
        }
        __syncthreads();
    }
    // ---- epilogue: bias, validity, target capture, row max ----
    int g = lane>>2, c4 = lane&3;
    #pragma unroll
    for(int mt=0;mt<4;mt++){
        #pragma unroll
        for(int half=0;half<2;half++){
            int rl = wm*64 + mt*16 + g + half*8;
            int r  = row0 + rl;
            int tg = (r<M2Q) ? g_tgt[r] : -1;
            float lm = -INFINITY;
            #pragma unroll
            for(int nt=0;nt<4;nt++){
                #pragma unroll
                for(int j=0;j<2;j++){
                    int c = col0 + wn*32 + nt*8 + c4*2 + j;
                    float v;
                    if(c<VQ){
                        v = acc[mt][nt][half*2+j] + bo[c];
                        if(c==tg) g_tok[r]=v;
                        lm = fmaxf(lm,v);
                    } else v = -INFINITY;
                    acc[mt][nt][half*2+j] = v;
                }
            }
            lm = fmaxf(lm, __shfl_xor_sync(0xffffffffu, lm, 1));
            lm = fmaxf(lm, __shfl_xor_sync(0xffffffffu, lm, 2));
            if(c4==0) red[rl][wn]=lm;
        }
    }
    __syncthreads();
    if(tid<128){
        float m=fmaxf(fmaxf(red[tid][0],red[tid][1]),fmaxf(red[tid][2],red[tid][3]));
        rowmax[tid]=m;
    }
    __syncthreads();
    #pragma unroll
    for(int mt=0;mt<4;mt++){
        #pragma unroll
        for(int half=0;half<2;half++){
            int rl = wm*64 + mt*16 + g + half*8;
            float rm = rowmax[rl];
            float s=0.f;
            #pragma unroll
            for(int nt=0;nt<4;nt++){
                #pragma unroll
                for(int j=0;j<2;j++){
                    float v = acc[mt][nt][half*2+j];
                    s += (v==-INFINITY) ? 0.f : __expf(v-rm);
                }
            }
            s += __shfl_xor_sync(0xffffffffu, s, 1);
            s += __shfl_xor_sync(0xffffffffu, s, 2);
            if(c4==0) red[rl][wn]=s;
        }
    }
    __syncthreads();
    if(tid<128){
        int r=row0+tid;
        if(r<M2Q){
            float s=red[tid][0]+red[tid][1]+red[tid][2]+red[tid][3];
            g_pm[(size_t)r*NVT + blockIdx.x]=rowmax[tid];
            g_ps[(size_t)r*NVT + blockIdx.x]=s;
        }
    }
}

// ---------------- combine LSE partials, accumulate p_log_prob ----------------
__global__ void k_lse_reduce(const int* __restrict__ attn){
    int r = blockIdx.x*blockDim.x + threadIdx.x;
    if(r>=M2Q) return;
    const float* pm = &g_pm[(size_t)r*NVT];
    const float* ps = &g_ps[(size_t)r*NVT];
    float m=-INFINITY;
    for(int q=0;q<NVT;q++) m=fmaxf(m,pm[q]);
    float s=0.f;
    for(int q=0;q<NVT;q++) s += ps[q]*__expf(pm[q]-m);
    float lse = m + __logf(s);
    float tlp = g_tok[r]-lse;
    int t=r/BQ, b=r%BQ;
    float mk=(float)attn[b*TQ + t + 1];
    atomicAdd(&g_acc[2], tlp*mk);
    atomicAdd(&g_acc[3], mk);
}

__global__ void k_finalize(float* __restrict__ out){
    out[0] = -(g_acc[2]/g_acc[3] + g_acc[0]/g_acc[1]);
}

// ---------------- launch ----------------
extern "C" void kernel_launch(void* const* d_in, const int* in_sizes, int n_in,
                              void* d_out, int out_size){
    const float* x_emb  = (const float*)d_in[0];
    const float* S      = (const float*)d_in[1];
    const float* emb    = (const float*)d_in[2];
    const float* W_ih   = (const float*)d_in[3];
    const float* W_hh   = (const float*)d_in[4];
    const float* b_lstm = (const float*)d_in[5];
    const float* W_out  = (const float*)d_in[6];
    const float* b_out  = (const float*)d_in[7];
    const float* gumbel = (const float*)d_in[8];
    const int*   x      = (const int*)d_in[9];
    const int*   attn   = (const int*)d_in[10];
    float* out = (float*)d_out;

    int lstm_smem = (32*HQ + BQ*HQ + 32*8) * (int)sizeof(float);
    cudaFuncSetAttribute(k_lstm_persist, cudaFuncAttributeMaxDynamicSharedMemorySize, lstm_smem);

    k_init<<<32,256>>>(x);
    k_cvt_wout<<<((size_t)NPAD*HQ/4 + 255)/256,256>>>(W_out);
    k_emission<<<256,256>>>(x_emb,S,attn);
    k_transition<<<50,256>>>(S);
    k_crf<<<1,256>>>(gumbel,out,out_size);
    k_decin<<<M2Q,128>>>(S,emb,x);
    k_gemm_xg<<<dim3(NGQ/128,16),256>>>(W_ih,b_lstm);
    k_lstm_persist<<<LBLK,256,lstm_smem>>>(W_hh);
    k_cvt_hall<<<(MPAD*HQ/4 + 255)/256,256>>>();
    k_gemm_lse_bf16<<<dim3(NVT,MPAD/128),256>>>(b_out);
    k_lse_reduce<<<8,256>>>(attn);
    k_finalize<<<1,1>>>(out);
}